// round 11
// baseline (speedup 1.0000x reference)
#include <cuda_runtime.h>
#include <cuda_fp16.h>
#include <mma.h>
#include <math.h>
#include <stdint.h>

using namespace nvcuda;

#define TT 256      // timesteps
#define BB 256      // batch
#define DD 1024     // hidden dim
#define WS 2048     // W row stride (W is (D, 2D) row-major: [Wx | Wh])

// fp16 copies (converted once per launch; deterministic)
__device__ __align__(16) __half g_W16[DD * WS];        // 4 MB
__device__ __align__(16) __half g_x16[(size_t)TT * BB * DD];  // 128 MB
__device__ __align__(16) __half g_h[BB * DD];          // 512 KB hidden-state shadow

// ===========================================================================
// Conversion kernels (fp32 -> fp16 RN)
// ===========================================================================
__global__ void __launch_bounds__(256) conv_w(const float* __restrict__ W)
{
    int i = blockIdx.x * blockDim.x + threadIdx.x;       // over DD*WS/4
    float4 v = *reinterpret_cast<const float4*>(W + (size_t)i * 4);
    __half2* p = reinterpret_cast<__half2*>(g_W16 + (size_t)i * 4);
    p[0] = __floats2half2_rn(v.x, v.y);
    p[1] = __floats2half2_rn(v.z, v.w);
}
__global__ void __launch_bounds__(256) conv_x(const float* __restrict__ x)
{
    size_t i = (size_t)blockIdx.x * blockDim.x + threadIdx.x;  // over TT*BB*DD/4
    float4 v = *reinterpret_cast<const float4*>(x + i * 4);
    __half2* p = reinterpret_cast<__half2*>(g_x16 + i * 4);
    p[0] = __floats2half2_rn(v.x, v.y);
    p[1] = __floats2half2_rn(v.z, v.w);
}

// ===========================================================================
// Fused persistent RNN: 128 blocks x 512 threads; block = (64 batch, 32 d).
//   acc = [x_t | h_{t-1}] @ Wrow[d, 0:2048]^T   (16 chunks of K=128)
//   h_t = tanh(acc + bias) -> out (fp32) + g_h (fp16)
//   W stripe (32 x 2048 fp16) resident in smem all 256 steps.
//   A chunks via cp.async, 4-slot ring, issued 3 ahead (x chunks of step t+1
//   are issued before the inter-step barrier).
//   4 batch groups of 32 blocks; acq/rel L2 barrier per group per step.
// ===========================================================================
#define P_CK 128                          // chunk K (halfs)
#define P_ALDH 136                        // A smem ldm (128+8 halfs)
#define P_WLDH 2056                       // W smem ldm (2048+8 halfs)
#define P_NSLOT 4
#define P_GRPBLK 32                       // blocks per barrier group

#define P_W_BYTES (32 * P_WLDH * 2)                   // 131584
#define P_SLOT_BYTES (64 * P_ALDH * 2)                // 17408
#define P_OFF_A P_W_BYTES                             // 131584
#define P_OFF_C0 (P_OFF_A + P_NSLOT * P_SLOT_BYTES)   // 201216
#define P_OFF_C1 (P_OFF_C0 + 64 * 32 * 4)             // 209408
#define P_SMEM_BYTES (P_OFF_C1 + 64 * 32 * 4)         // 217600

__device__ __align__(256) unsigned g_cnt[4 * 64];
__device__ __align__(256) unsigned g_phase[4 * 64];   // monotonic across replays

__device__ __forceinline__ unsigned bar_arrive_acqrel(unsigned* p) {
    unsigned old;
    asm volatile("atom.acq_rel.gpu.add.u32 %0,[%1],1;"
                 : "=r"(old) : "l"(p) : "memory");
    return old;
}
__device__ __forceinline__ void bar_reset_relaxed(unsigned* p) {
    asm volatile("st.relaxed.gpu.u32 [%0],0;" :: "l"(p) : "memory");
}
__device__ __forceinline__ void bar_release(unsigned* p) {
    asm volatile("red.release.gpu.add.u32 [%0],1;" :: "l"(p) : "memory");
}
__device__ __forceinline__ unsigned bar_poll_acquire(const unsigned* p) {
    unsigned v;
    asm volatile("ld.acquire.gpu.u32 %0,[%1];" : "=r"(v) : "l"(p) : "memory");
    return v;
}
__device__ __forceinline__ void cp16(uint32_t saddr, const void* gptr) {
    asm volatile("cp.async.cg.shared.global [%0], [%1], 16;"
                 :: "r"(saddr), "l"(gptr));
}

__global__ void __launch_bounds__(512)
rnn_fused(const float* __restrict__ bias, float* __restrict__ out)
{
    extern __shared__ char smraw[];
    __half* sW = (__half*)smraw;
    __half* sA[P_NSLOT];
    #pragma unroll
    for (int s = 0; s < P_NSLOT; ++s)
        sA[s] = (__half*)(smraw + P_OFF_A + s * P_SLOT_BYTES);
    float* sC0 = (float*)(smraw + P_OFF_C0);
    float* sC1 = (float*)(smraw + P_OFF_C1);
    __shared__ float sBias[32];
    __shared__ unsigned s_base;

    const int tid = threadIdx.x;
    const int wid = tid >> 5;             // 16 warps = 4(M) x 2(N) x 2(Ksplit)
    const int wM = wid & 3;               // 4 x 16 rows = 64
    const int wN = (wid >> 2) & 1;        // 2 x 16 cols = 32
    const int kS = wid >> 3;              // K split within 128-chunk

    const int ds = blockIdx.x & 31;       // 32 d-stripes of 32
    const int bg = blockIdx.x >> 5;       // 4 batch groups of 64
    const int d0 = ds * 32;
    const int b0 = bg * 64;

    unsigned* cntp   = &g_cnt[bg * 64];
    unsigned* phasep = &g_phase[bg * 64];

    uint32_t sA_u32[P_NSLOT];
    #pragma unroll
    for (int s = 0; s < P_NSLOT; ++s)
        sA_u32[s] = (uint32_t)__cvta_generic_to_shared(sA[s]);

    // --- Load W stripe (rows d0..d0+31, 2048 cols fp16) once ---
    #pragma unroll
    for (int j = 0; j < 16; ++j) {
        int f   = tid + j * 512;          // 8192 16B-segments
        int row = f >> 8;                 // 256 segs per row
        int sg  = f & 255;
        int4 v = *reinterpret_cast<const int4*>(
            &g_W16[(size_t)(d0 + row) * WS + sg * 8]);
        *reinterpret_cast<int4*>(&sW[row * P_WLDH + sg * 8]) = v;
    }
    if (tid < 32) sBias[tid] = bias[d0 + tid];
    if (tid == 0) s_base = bar_poll_acquire(phasep);
    __syncthreads();
    const unsigned base = s_base;

    // --- chunk issue cursor: global stream of chunks.
    // step 0 has 8 chunks (x only); steps 1..255 have 16 (x 0..7, h 8..15).
    int tI = 0, cI = 0, isl = 0;
    auto issue_next = [&]() {
        if (tI >= TT) return;
        const bool is_x = (tI == 0) || (cI < 8);
        #pragma unroll
        for (int j = 0; j < 2; ++j) {
            int f   = tid + j * 512;      // 1024 segs: 64 rows x 16 segs
            int row = f >> 4;
            int sg  = f & 15;
            const void* src;
            if (is_x)
                src = &g_x16[((size_t)tI * BB + b0 + row) * DD + cI * P_CK + sg * 8];
            else
                src = &g_h[(size_t)(b0 + row) * DD + (cI - 8) * P_CK + sg * 8];
            cp16(sA_u32[isl] + (uint32_t)(row * P_ALDH + sg * 8) * 2u, src);
        }
        asm volatile("cp.async.commit_group;");
        isl = (isl + 1) & 3;
        if (++cI == ((tI == 0) ? 8 : 16)) { cI = 0; ++tI; }
    };

    // prologue: 3 chunks in flight
    issue_next(); issue_next(); issue_next();

    // epilogue map: 64 rows x 8 float4
    const int erow = tid >> 3;
    const int ec4  = tid & 7;

    int csl = 0;
    for (int t = 0; t < TT; ++t) {
        const int nch = (t == 0) ? 8 : 16;

        wmma::fragment<wmma::accumulator, 16, 16, 16, float> acc[2];
        wmma::fill_fragment(acc[0], 0.0f);
        wmma::fill_fragment(acc[1], 0.0f);

        for (int c = 0; c < nch; ++c) {
            asm volatile("cp.async.wait_group 2;");
            __syncthreads();              // chunk c present; slot (c+3)&3 free
            issue_next();                 // chunk c+3 of the global stream

            const __half* ap = &sA[csl][wM * 16 * P_ALDH + kS * 64];
            const __half* bp = &sW[(wN * 16) * P_WLDH + c * P_CK + kS * 64];
            #pragma unroll
            for (int kk = 0; kk < 64; kk += 16) {
                wmma::fragment<wmma::matrix_a, 16, 16, 16, __half, wmma::row_major> a;
                wmma::fragment<wmma::matrix_b, 16, 16, 16, __half, wmma::col_major> b;
                wmma::load_matrix_sync(a, ap + kk, P_ALDH);
                wmma::load_matrix_sync(b, bp + kk, P_WLDH);
                wmma::mma_sync(acc[(kk >> 4) & 1], a, b, acc[(kk >> 4) & 1]);
            }
            csl = (csl + 1) & 3;
        }

        // combine: 2 accs within warp, 2 kSplit warps via sC0/sC1
        #pragma unroll
        for (int e = 0; e < acc[0].num_elements; ++e)
            acc[0].x[e] += acc[1].x[e];
        wmma::store_matrix_sync((kS ? sC1 : sC0) + (wM * 16) * 32 + wN * 16,
                                acc[0], 32, wmma::mem_row_major);
        __syncthreads();

        // epilogue: + bias, tanh -> out fp32 (write-once) + g_h fp16
        {
            const float* c0 = &sC0[erow * 32 + ec4 * 4];
            const float* c1 = &sC1[erow * 32 + ec4 * 4];
            float bx = sBias[ec4 * 4 + 0], by = sBias[ec4 * 4 + 1];
            float bz = sBias[ec4 * 4 + 2], bw = sBias[ec4 * 4 + 3];
            float4 o;
            o.x = tanhf(c0[0] + c1[0] + bx);
            o.y = tanhf(c0[1] + c1[1] + by);
            o.z = tanhf(c0[2] + c1[2] + bz);
            o.w = tanhf(c0[3] + c1[3] + bw);
            __stcg(reinterpret_cast<float4*>(
                &out[((size_t)((b0 + erow) * TT + t)) * DD + d0 + ec4 * 4]), o);
            union { uint2 u; __half2 h2[2]; } pk;
            pk.h2[0] = __floats2half2_rn(o.x, o.y);
            pk.h2[1] = __floats2half2_rn(o.z, o.w);
            __stcg(reinterpret_cast<uint2*>(
                &g_h[(size_t)(b0 + erow) * DD + d0 + ec4 * 4]), pk.u);
        }

        // group barrier (32 blocks sharing this batch group), skip after last.
        // NOTE: up to 3 x-chunks of step t+1 are already in flight — they do
        // not depend on h, so issuing them before the barrier is safe.
        if (t != TT - 1) {
            __syncthreads();
            if (tid == 0) {
                unsigned old = bar_arrive_acqrel(cntp);
                if (old == P_GRPBLK - 1) {
                    bar_reset_relaxed(cntp);
                    bar_release(phasep);
                } else {
                    const unsigned target = base + (unsigned)(t + 1);
                    while ((int)(bar_poll_acquire(phasep) - target) < 0) { }
                }
            }
            __syncthreads();
        }
    }
}

// ===========================================================================
// Launch
// ===========================================================================
extern "C" void kernel_launch(void* const* d_in, const int* in_sizes, int n_in,
                              void* d_out, int out_size)
{
    const float* x    = (const float*)d_in[0];
    const float* W    = (const float*)d_in[1];
    const float* bias = (const float*)d_in[2];
    float* out = (float*)d_out;

    cudaFuncSetAttribute(rnn_fused, cudaFuncAttributeMaxDynamicSharedMemorySize,
                         P_SMEM_BYTES);

    conv_w<<<(DD * WS / 4) / 256, 256>>>(W);
    conv_x<<<(int)(((size_t)TT * BB * DD / 4) / 256), 256>>>(x);
    rnn_fused<<<128, 512, P_SMEM_BYTES>>>(bias, out);
}

// round 13
// speedup vs baseline: 1.3789x; 1.3789x over previous
#include <cuda_runtime.h>
#include <cuda_fp16.h>
#include <mma.h>
#include <math.h>
#include <stdint.h>

using namespace nvcuda;

#define TT 256      // timesteps
#define BB 256      // batch
#define DD 1024     // hidden dim
#define WS 2048     // W row stride (W is (D, 2D) row-major)

// fp16 shadow of the hidden state, written each step; A-operand source.
__device__ __align__(16) __half g_h[BB * DD];   // 512 KB

// ===========================================================================
// Kernel 1: preactivations, fp16 wmma (fp32 accum), 128x128 tile.  (R10)
//   out[(b*TT + t)*DD + d] = bias[d] + sum_k x[(t*BB+b)*DD + k] * W[d*WS + k]
// ===========================================================================
#define X_BM 128
#define X_BN 128
#define X_BK 32
#define X_LDH 40                          // smem ldm in halfs (80B rows)
#define X_TILEH (X_BM * X_LDH)            // 5120 halfs = 10240 B
#define X_SMEM_BYTES 65536                // max(4 tiles = 40960, sC = 65536)

__global__ void __launch_bounds__(256)
gemm_x_f16(const float* __restrict__ x, const float* __restrict__ W,
           const float* __restrict__ bias, float* __restrict__ out)
{
    extern __shared__ char smraw[];
    __half* sA[2] = { (__half*)smraw,                 (__half*)(smraw + 2 * X_TILEH * 2) };
    __half* sB[2] = { (__half*)(smraw + X_TILEH * 2), (__half*)(smraw + 3 * X_TILEH * 2) };

    const int r0  = blockIdx.y * X_BM;    // row tile in (t*BB + b) space
    const int d0  = blockIdx.x * X_BN;
    const int tid = threadIdx.x;
    const int wid = tid >> 5;
    const int warpM = wid & 3;            // 4 x 32 rows
    const int warpN = wid >> 2;           // 2 x 64 cols

    wmma::fragment<wmma::accumulator, 16, 16, 16, float> acc[2][4];
    #pragma unroll
    for (int mi = 0; mi < 2; ++mi)
        #pragma unroll
        for (int ni = 0; ni < 4; ++ni)
            wmma::fill_fragment(acc[mi][ni], 0.0f);

    auto load_chunk = [&](int k0, __half* dA, __half* dB) {
        #pragma unroll
        for (int j = 0; j < 4; ++j) {
            int f   = tid + j * 256;      // 1024 float4
            int row = f >> 3;             // 8 float4 per row (32 floats)
            int c4  = f & 7;
            float4 va = *reinterpret_cast<const float4*>(
                &x[(size_t)(r0 + row) * DD + k0 + c4 * 4]);
            __half2* pa = reinterpret_cast<__half2*>(&dA[row * X_LDH + c4 * 4]);
            pa[0] = __floats2half2_rn(va.x, va.y);
            pa[1] = __floats2half2_rn(va.z, va.w);
            float4 vb = *reinterpret_cast<const float4*>(
                &W[(size_t)(d0 + row) * WS + k0 + c4 * 4]);
            __half2* pb = reinterpret_cast<__half2*>(&dB[row * X_LDH + c4 * 4]);
            pb[0] = __floats2half2_rn(vb.x, vb.y);
            pb[1] = __floats2half2_rn(vb.z, vb.w);
        }
    };

    load_chunk(0, sA[0], sB[0]);
    __syncthreads();

    const int NCH = DD / X_BK;            // 32 chunks
    for (int c = 0; c < NCH; ++c) {
        int cur = c & 1;
        if (c + 1 < NCH) load_chunk((c + 1) * X_BK, sA[cur ^ 1], sB[cur ^ 1]);

        #pragma unroll
        for (int kk = 0; kk < X_BK; kk += 16) {
            wmma::fragment<wmma::matrix_a, 16, 16, 16, __half, wmma::row_major> a[2];
            #pragma unroll
            for (int mi = 0; mi < 2; ++mi)
                wmma::load_matrix_sync(a[mi], &sA[cur][(warpM * 32 + mi * 16) * X_LDH + kk], X_LDH);
            #pragma unroll
            for (int ni = 0; ni < 4; ++ni) {
                wmma::fragment<wmma::matrix_b, 16, 16, 16, __half, wmma::col_major> b;
                wmma::load_matrix_sync(b, &sB[cur][(warpN * 64 + ni * 16) * X_LDH + kk], X_LDH);
                #pragma unroll
                for (int mi = 0; mi < 2; ++mi)
                    wmma::mma_sync(acc[mi][ni], a[mi], b, acc[mi][ni]);
            }
        }
        __syncthreads();
    }

    // Stage C (fp32) in smem, overlaying the fp16 tiles
    float* sC = (float*)smraw;
    #pragma unroll
    for (int mi = 0; mi < 2; ++mi)
        #pragma unroll
        for (int ni = 0; ni < 4; ++ni)
            wmma::store_matrix_sync(&sC[(warpM * 32 + mi * 16) * X_BN + warpN * 64 + ni * 16],
                                    acc[mi][ni], X_BN, wmma::mem_row_major);
    __syncthreads();

    // Epilogue: +bias, scatter. Block spans 128 rows => t constant.
    const int t = r0 >> 8;
    const int bbase = r0 & 255;
    #pragma unroll
    for (int j = 0; j < 16; ++j) {
        int f   = tid + j * 256;          // 4096 float4
        int row = f >> 5;                 // 32 float4 per row
        int c4  = f & 31;
        float4 bv = *reinterpret_cast<const float4*>(&bias[d0 + c4 * 4]);
        const float* cp = &sC[row * X_BN + c4 * 4];
        float4 o;
        o.x = cp[0] + bv.x; o.y = cp[1] + bv.y; o.z = cp[2] + bv.z; o.w = cp[3] + bv.w;
        *reinterpret_cast<float4*>(
            &out[((size_t)((bbase + row) * TT + t)) * DD + d0 + c4 * 4]) = o;
    }
}

// ===========================================================================
// Kernel 2: persistent recurrence, fp16 operands, fp32 accum.
//   - 128 blocks x 512 threads; block tile = 32 batch x 64 d.
//   - Wh stripe (64 x 1024 fp16, 132 KB) resident in smem for all steps.
//   - FULL h tile (32 x 1024 fp16, 66 KB) loaded per step in ONE shot via
//     cp.async (2 commit halves); latency paid once/step, 2 syncs/step.
//   - 16 warps = 2(M) x 4(N) x 2(K-half); combine via smem C0/C1.
//   - 8 independent batch groups of 16 blocks; acq/rel barrier.
// ===========================================================================
#define RH_BM 32
#define RH_BN 64
#define RH_CK 128                         // K per compute chunk
#define RH_WLDH 1032                      // Wh ldm in halfs (1024+8)
#define RH_ALDH 1032                      // h  ldm in halfs (1024+8)
#define RH_GRPBLK 16                      // blocks per barrier group

#define RH_WH_BYTES (RH_BN * RH_WLDH * 2)             // 132096
#define RH_A_BYTES  (RH_BM * RH_ALDH * 2)             // 66048
#define RH_C_BYTES  (RH_BM * RH_BN * 4)               // 8192
#define RH_OFF_A  RH_WH_BYTES                         // 132096
#define RH_OFF_C0 (RH_OFF_A + RH_A_BYTES)             // 198144
#define RH_OFF_C1 (RH_OFF_C0 + RH_C_BYTES)            // 206336
#define RH_SMEM_BYTES (RH_OFF_C1 + RH_C_BYTES)        // 214528

__device__ __align__(256) unsigned g_cnt[8 * 64];
__device__ __align__(256) unsigned g_phase[8 * 64];   // monotonic across replays

__device__ __forceinline__ unsigned bar_arrive_acqrel(unsigned* p) {
    unsigned old;
    asm volatile("atom.acq_rel.gpu.add.u32 %0,[%1],1;"
                 : "=r"(old) : "l"(p) : "memory");
    return old;
}
__device__ __forceinline__ void bar_reset_relaxed(unsigned* p) {
    asm volatile("st.relaxed.gpu.u32 [%0],0;" :: "l"(p) : "memory");
}
__device__ __forceinline__ void bar_release(unsigned* p) {
    asm volatile("red.release.gpu.add.u32 [%0],1;" :: "l"(p) : "memory");
}
__device__ __forceinline__ unsigned bar_poll_acquire(const unsigned* p) {
    unsigned v;
    asm volatile("ld.acquire.gpu.u32 %0,[%1];" : "=r"(v) : "l"(p) : "memory");
    return v;
}
__device__ __forceinline__ void cp16(uint32_t saddr, const void* gptr) {
    asm volatile("cp.async.cg.shared.global [%0], [%1], 16;"
                 :: "r"(saddr), "l"(gptr));
}

__global__ void __launch_bounds__(512)
rnn_persistent(const float* __restrict__ W, float* __restrict__ out)
{
    extern __shared__ char smraw[];
    __half* sWh = (__half*)smraw;
    __half* sA  = (__half*)(smraw + RH_OFF_A);
    float*  sC[2] = { (float*)(smraw + RH_OFF_C0), (float*)(smraw + RH_OFF_C1) };
    __shared__ unsigned s_base;

    const int tid = threadIdx.x;
    const int wid = tid >> 5;             // 16 warps
    const int wM    = wid & 1;            // 2 x 16 rows = 32
    const int wN    = (wid >> 1) & 3;     // 4 x 16 cols = 64
    const int kHalf = wid >> 3;           // 2-way K split within 128 chunk

    const int nT = blockIdx.x & 15;       // 16 d-stripes of 64
    const int mT = blockIdx.x >> 4;       // 8 batch groups of 32 (barrier scope)
    const int d0 = nT * RH_BN;
    const int b0 = mT * RH_BM;

    unsigned* cntp   = &g_cnt[mT * 64];
    unsigned* phasep = &g_phase[mT * 64];

    const uint32_t sA_u32 = (uint32_t)__cvta_generic_to_shared(sA);

    // --- Load Wh stripe once (fp32 -> fp16 RN): sWh[d][k], d = 0..63 ---
    {
        const float* Wh = W + DD;
        #pragma unroll
        for (int j = 0; j < 32; ++j) {
            int f   = tid + j * 512;      // 16384 float4
            int row = f >> 8;             // 256 float4 per row
            int c4  = f & 255;
            float4 v = *reinterpret_cast<const float4*>(
                &Wh[(size_t)(d0 + row) * WS + c4 * 4]);
            __half2* p = reinterpret_cast<__half2*>(&sWh[row * RH_WLDH + c4 * 4]);
            p[0] = __floats2half2_rn(v.x, v.y);
            p[1] = __floats2half2_rn(v.z, v.w);
        }
    }

    if (tid == 0) s_base = bar_poll_acquire(phasep);
    __syncthreads();
    const unsigned base = s_base;

    // full h tile: 32 rows x 1024 halfs = 4096 x 16B segs; 8 per thread.
    // half 0 = k [0,512) (4 segs/thread), half 1 = k [512,1024).
    auto issue_half = [&](int h) {
        #pragma unroll
        for (int j = 0; j < 4; ++j) {
            int f   = tid + j * 512;      // 2048 segs: 32 rows x 64 segs
            int row = f >> 6;
            int sg  = (f & 63) + h * 64;
            const void* g = &g_h[(size_t)(b0 + row) * DD + sg * 8];
            uint32_t s = sA_u32 + (uint32_t)(row * RH_ALDH + sg * 8) * 2u;
            cp16(s, g);
        }
        asm volatile("cp.async.commit_group;");
    };

    // epilogue map: 32x64 floats = 512 float4, 1 per thread
    const int erow = tid >> 4;            // 16 float4 per row
    const int ec4  = tid & 15;

    for (int t = 0; t < TT; ++t) {
        if (t == 0) {
            float* p = &out[((size_t)((b0 + erow) * TT + 0)) * DD + d0 + ec4 * 4];
            float4 v = __ldcg(reinterpret_cast<const float4*>(p));
            v.x = tanhf(v.x); v.y = tanhf(v.y); v.z = tanhf(v.z); v.w = tanhf(v.w);
            *reinterpret_cast<float4*>(p) = v;
            union { uint2 u; __half2 h2[2]; } pk;
            pk.h2[0] = __floats2half2_rn(v.x, v.y);
            pk.h2[1] = __floats2half2_rn(v.z, v.w);
            __stcg(reinterpret_cast<uint2*>(
                &g_h[(size_t)(b0 + erow) * DD + d0 + ec4 * 4]), pk.u);
        } else {
            // issue the whole h tile immediately (both halves in flight)
            issue_half(0);
            issue_half(1);

            // prefetch preactivation while h streams
            float* eptr = &out[((size_t)((b0 + erow) * TT + t)) * DD + d0 + ec4 * 4];
            float4 pre = __ldcg(reinterpret_cast<const float4*>(eptr));

            wmma::fragment<wmma::accumulator, 16, 16, 16, float> acc[2];
            wmma::fill_fragment(acc[0], 0.0f);
            wmma::fill_fragment(acc[1], 0.0f);

            // first half arrived -> compute chunks 0..3 while half 2 lands
            asm volatile("cp.async.wait_group 1;");
            __syncthreads();
            #pragma unroll
            for (int c = 0; c < 4; ++c) {
                const __half* ap = &sA[wM * 16 * RH_ALDH + c * RH_CK + kHalf * 64];
                const __half* bp = &sWh[(wN * 16) * RH_WLDH + c * RH_CK + kHalf * 64];
                #pragma unroll
                for (int kk = 0; kk < 64; kk += 16) {
                    wmma::fragment<wmma::matrix_a, 16, 16, 16, __half, wmma::row_major> a;
                    wmma::fragment<wmma::matrix_b, 16, 16, 16, __half, wmma::col_major> b;
                    wmma::load_matrix_sync(a, ap + kk, RH_ALDH);
                    wmma::load_matrix_sync(b, bp + kk, RH_WLDH);
                    wmma::mma_sync(acc[(kk >> 4) & 1], a, b, acc[(kk >> 4) & 1]);
                }
            }
            asm volatile("cp.async.wait_group 0;");
            __syncthreads();
            #pragma unroll
            for (int c = 4; c < 8; ++c) {
                const __half* ap = &sA[wM * 16 * RH_ALDH + c * RH_CK + kHalf * 64];
                const __half* bp = &sWh[(wN * 16) * RH_WLDH + c * RH_CK + kHalf * 64];
                #pragma unroll
                for (int kk = 0; kk < 64; kk += 16) {
                    wmma::fragment<wmma::matrix_a, 16, 16, 16, __half, wmma::row_major> a;
                    wmma::fragment<wmma::matrix_b, 16, 16, 16, __half, wmma::col_major> b;
                    wmma::load_matrix_sync(a, ap + kk, RH_ALDH);
                    wmma::load_matrix_sync(b, bp + kk, RH_WLDH);
                    wmma::mma_sync(acc[(kk >> 4) & 1], a, b, acc[(kk >> 4) & 1]);
                }
            }

            // reduce 2 accs within warp, combine kHalf warps via smem
            #pragma unroll
            for (int e = 0; e < acc[0].num_elements; ++e)
                acc[0].x[e] += acc[1].x[e];
            wmma::store_matrix_sync(&sC[kHalf][(wM * 16) * RH_BN + wN * 16],
                                    acc[0], RH_BN, wmma::mem_row_major);
            __syncthreads();

            // epilogue: sC0 + sC1 + preact -> tanh -> out (fp32) + g_h (fp16)
            {
                const float* c0 = &sC[0][erow * RH_BN + ec4 * 4];
                const float* c1 = &sC[1][erow * RH_BN + ec4 * 4];
                float4 o;
                o.x = tanhf(pre.x + c0[0] + c1[0]);
                o.y = tanhf(pre.y + c0[1] + c1[1]);
                o.z = tanhf(pre.z + c0[2] + c1[2]);
                o.w = tanhf(pre.w + c0[3] + c1[3]);
                *reinterpret_cast<float4*>(eptr) = o;
                union { uint2 u; __half2 h2[2]; } pk;
                pk.h2[0] = __floats2half2_rn(o.x, o.y);
                pk.h2[1] = __floats2half2_rn(o.z, o.w);
                __stcg(reinterpret_cast<uint2*>(
                    &g_h[(size_t)(b0 + erow) * DD + d0 + ec4 * 4]), pk.u);
            }
        }

        // group barrier (16 blocks sharing this batch group), skip after last
        if (t != TT - 1) {
            __syncthreads();
            if (tid == 0) {
                unsigned old = bar_arrive_acqrel(cntp);
                if (old == RH_GRPBLK - 1) {
                    bar_reset_relaxed(cntp);
                    bar_release(phasep);
                } else {
                    const unsigned target = base + (unsigned)(t + 1);
                    while ((int)(bar_poll_acquire(phasep) - target) < 0) { }
                }
            }
            __syncthreads();
        }
    }
}

// ===========================================================================
// Launch
// ===========================================================================
extern "C" void kernel_launch(void* const* d_in, const int* in_sizes, int n_in,
                              void* d_out, int out_size)
{
    const float* x    = (const float*)d_in[0];
    const float* W    = (const float*)d_in[1];
    const float* bias = (const float*)d_in[2];
    float* out = (float*)d_out;

    cudaFuncSetAttribute(gemm_x_f16, cudaFuncAttributeMaxDynamicSharedMemorySize,
                         X_SMEM_BYTES);
    cudaFuncSetAttribute(rnn_persistent, cudaFuncAttributeMaxDynamicSharedMemorySize,
                         RH_SMEM_BYTES);

    dim3 g1(DD / X_BN, (TT * BB) / X_BM);   // (8, 512)
    gemm_x_f16<<<g1, 256, X_SMEM_BYTES>>>(x, W, bias, out);

    rnn_persistent<<<128, 512, RH_SMEM_BYTES>>>(W, out);
}